// round 14
// baseline (speedup 1.0000x reference)
#include <cuda_runtime.h>

#define BDIM 64
#define WPB 2             // warps (MLPs) per block
#define RSC 68            // rec row stride; mult of 4 (16B align), ==4 mod 32
#define NROWS 51
#define RECW (NROWS * RSC)
#define PSTRIDE 264
#define NS 150

typedef unsigned long long u64;

__constant__ float c_lr[6] = {0.001f, 0.01f, 0.05f, 0.1f, 0.5f, 1.0f};
__device__ float g_sumsq = 0.f;   // zeroed by k_zero at END of each call

__device__ __forceinline__ float clip1e4(float v) {
    return fminf(fmaxf(v, -10000.f), 10000.f);
}
__device__ __forceinline__ u64 pk(float lo, float hi) {
    u64 r; asm("mov.b64 %0, {%1,%2};" : "=l"(r) : "f"(lo), "f"(hi)); return r;
}
__device__ __forceinline__ void upk(u64 v, float& lo, float& hi) {
    asm("mov.b64 {%0,%1}, %2;" : "=f"(lo), "=f"(hi) : "l"(v));
}
__device__ __forceinline__ u64 ffma2(u64 a, u64 b, u64 c) {
    u64 d; asm("fma.rn.f32x2 %0, %1, %2, %3;" : "=l"(d) : "l"(a), "l"(b), "l"(c));
    return d;
}
__device__ __forceinline__ u64 add2(u64 a, u64 b) {
    u64 d; asm("add.rn.f32x2 %0, %1, %2;" : "=l"(d) : "l"(a), "l"(b)); return d;
}

__global__ void k_zero() { g_sumsq = 0.f; }

// rec row map (per warp):
//  0..9  dhm    10..19 h1    20..29 dg    30..39 h2
//  43 x0  48 x1  44 x2  49 x3     45 d0  50 d1  47 d2
__global__ void __launch_bounds__(BDIM, 7) k_main(
    const float* __restrict__ W1, const float* __restrict__ b1,
    const float* __restrict__ W2, const float* __restrict__ b2,
    const float* __restrict__ W3, const float* __restrict__ b3,
    const float* __restrict__ G1, const float* __restrict__ G2,
    const float* __restrict__ G3, const float* __restrict__ G4,
    const float* __restrict__ G5, const float* __restrict__ G6,
    const float* __restrict__ dx, const float* __restrict__ fv,
    const int* __restrict__ dy, const int* __restrict__ ss,
    float* __restrict__ out)
{
    __shared__ __align__(16) float ps[WPB * PSTRIDE];
    __shared__ __align__(16) float rec[WPB * RECW];

    const int tid  = threadIdx.x;
    const int lane = tid & 31;
    const int warp = tid >> 5;
    const int b    = blockIdx.x * WPB + warp;

    float* P    = ps  + warp * PSTRIDE;
    float* recW = rec + warp * RECW;
    // P layout: 0:W1[10x4] 40:b1[10] 52:W2 rows stride 12 (10 rows)
    // 172:b2[10] 184:W3 rows stride 12 (3 rows) 220:b3[3] 224:W3^T stride 4

    const float lr = c_lr[ss[b]];
    float* wout = out + (size_t)b * 388;

    for (int k = lane; k < PSTRIDE; k += 32) P[k] = 0.f;
    __syncwarp();
    for (int k = lane; k < 40; k += 32) {
        float p = fmaf(-lr, G1[b * 40 + k], W1[b * 40 + k]);
        P[k] = p; wout[k] = clip1e4(p);
    }
    for (int k = lane; k < 10; k += 32) {
        float p = fmaf(-lr, G2[b * 10 + k], b1[b * 10 + k]);
        P[40 + k] = p; wout[40 + k] = clip1e4(p);
    }
    for (int k = lane; k < 100; k += 32) {
        float p = fmaf(-lr, G3[b * 100 + k], W2[b * 100 + k]);
        int r = k / 10, c = k - r * 10;
        P[52 + 12 * r + c] = p; wout[50 + k] = clip1e4(p);
    }
    for (int k = lane; k < 10; k += 32) {
        float p = fmaf(-lr, G4[b * 10 + k], b2[b * 10 + k]);
        P[172 + k] = p; wout[150 + k] = clip1e4(p);
    }
    for (int k = lane; k < 30; k += 32) {
        float p = fmaf(-lr, G5[b * 30 + k], W3[b * 30 + k]);
        int r = k / 10, c = k - r * 10;
        P[184 + 12 * r + c] = p;
        P[224 + 4 * c + r]  = p;                 // W3^T (rows stride 4)
        wout[160 + k] = clip1e4(p);
    }
    for (int k = lane; k < 3; k += 32) {
        float p = fmaf(-lr, G6[b * 3 + k], b3[b * 3 + k]);
        P[220 + k] = p; wout[190 + k] = clip1e4(p);
    }
    __syncwarp();

    // ---- minipass offsets (floats from recW), bank-planned ----
    int oa0, oa1, ob0, ob1;                 // tile-set 1: gW2 5x5 pair tiles
    {
        int q = (lane < 25) ? lane / 5 : 0;
        int r = (lane < 25) ? lane % 5 : 0;
        oa0 = (20 + q) * RSC; oa1 = (25 + q) * RSC;   // dg rows (A)
        ob0 = (10 + r) * RSC; ob1 = (15 + r) * RSC;   // h1 rows (B)
    }
    int oe0, oe1, of0, of1;                 // tile-set 2: gW1 / gW3
    if (lane < 10) {
        int a = lane >> 1, bq = lane & 1;
        oe0 = a * RSC; oe1 = (a + 5) * RSC;                  // dhm rows
        of0 = (bq ? 44 : 43) * RSC; of1 = (bq ? 49 : 48) * RSC; // x rows
    } else if (lane < 20) {
        int l = lane - 10, p = l / 5, qh = l % 5;
        oe0 = (p ? 47 : 45) * RSC; oe1 = 50 * RSC;           // d rows
        of0 = (30 + qh) * RSC; of1 = (35 + qh) * RSC;        // h2 rows
    } else {
        oe0 = 0; oe1 = 5 * RSC; of0 = 43 * RSC; of1 = 48 * RSC; // dummies
    }

    u64 m0 = 0ull, m1 = 0ull, m2 = 0ull, m3 = 0ull;
    u64 m4 = 0ull, m5 = 0ull, m6 = 0ull, m7 = 0ull;
    u64 sa0 = 0ull, sa1 = 0ull, se0 = 0ull, se1 = 0ull;   // bias sums

    float l0acc = 0.f, l1acc = 0.f;
    const float invN = 1.f / 150.f;
    const int cj = 2 * lane;

#pragma unroll 1
    for (int c = 0; c < 3; c++) {
        const int s0 = 64 * c + cj;
        const bool m = (s0 < NS);           // NS even, s0 even -> one mask
        float4 xa = make_float4(0.f, 0.f, 0.f, 0.f);
        float4 xb = xa;
        int2 y01 = make_int2(0, 0);
        if (m) {
            xa = ((const float4*)dx)[s0];
            xb = ((const float4*)dx)[s0 + 1];
            y01 = *(const int2*)&dy[s0];
        }
        *(u64*)&recW[43 * RSC + cj] = pk(xa.x, xb.x);
        *(u64*)&recW[48 * RSC + cj] = pk(xa.y, xb.y);
        *(u64*)&recW[44 * RSC + cj] = pk(xa.z, xb.z);
        *(u64*)&recW[49 * RSC + cj] = pk(xa.w, xb.w);

        // layer 1 (scalar, two samples, bias folded into chain head)
        // relu mask packed: bit h = sample a, bit 16+h = sample b
        float h1a[10], h1b[10];
        unsigned msk1 = 0u;
#pragma unroll
        for (int h = 0; h < 10; h++) {
            float4 w = *(const float4*)&P[4 * h];
            float bb = P[40 + h];
            float pa = fmaf(w.x, xa.x, fmaf(w.y, xa.y, bb));
            float qa = fmaf(w.z, xa.z, w.w * xa.w);
            float va = fmaxf(pa + qa, 0.f);
            float pb = fmaf(w.x, xb.x, fmaf(w.y, xb.y, bb));
            float qb = fmaf(w.z, xb.z, w.w * xb.w);
            float vb = fmaxf(pb + qb, 0.f);
            msk1 |= (va > 0.f) ? (1u << h) : 0u;
            msk1 |= (vb > 0.f) ? (1u << (16 + h)) : 0u;
            h1a[h] = va; h1b[h] = vb;
            *(u64*)&recW[(10 + h) * RSC + cj] = pk(va, vb);
        }
        // layer 2 (scalar; h1 arrays die here)
        float h2a[10], h2b[10];
        unsigned msk2 = 0u;
#pragma unroll
        for (int g = 0; g < 10; g++) {
            const float* r = &P[52 + 12 * g];
            float4 wA = *(const float4*)r;
            float4 wB = *(const float4*)(r + 4);
            float2 wC = *(const float2*)(r + 8);
            float bb = P[172 + g];
            float pa = fmaf(wA.x, h1a[0], fmaf(wA.z, h1a[2],
                       fmaf(wB.x, h1a[4], fmaf(wB.z, h1a[6], wC.x * h1a[8]))));
            float qa = fmaf(wA.y, h1a[1], fmaf(wA.w, h1a[3],
                       fmaf(wB.y, h1a[5], fmaf(wB.w, h1a[7],
                       fmaf(wC.y, h1a[9], bb)))));
            float va = fmaxf(pa + qa, 0.f);
            float pb = fmaf(wA.x, h1b[0], fmaf(wA.z, h1b[2],
                       fmaf(wB.x, h1b[4], fmaf(wB.z, h1b[6], wC.x * h1b[8]))));
            float qb = fmaf(wA.y, h1b[1], fmaf(wA.w, h1b[3],
                       fmaf(wB.y, h1b[5], fmaf(wB.w, h1b[7],
                       fmaf(wC.y, h1b[9], bb)))));
            float vb = fmaxf(pb + qb, 0.f);
            msk2 |= (va > 0.f) ? (1u << g) : 0u;
            msk2 |= (vb > 0.f) ? (1u << (16 + g)) : 0u;
            h2a[g] = va; h2b[g] = vb;
            *(u64*)&recW[(30 + g) * RSC + cj] = pk(va, vb);
        }
        // layer 3 logits (scalar; h2 arrays die here)
        float lgl[3], lgh[3];
#pragma unroll
        for (int o = 0; o < 3; o++) {
            const float* r = &P[184 + 12 * o];
            float4 wA = *(const float4*)r;
            float4 wB = *(const float4*)(r + 4);
            float2 wC = *(const float2*)(r + 8);
            float bb = P[220 + o];
            float pa = fmaf(wA.x, h2a[0], fmaf(wA.z, h2a[2],
                       fmaf(wB.x, h2a[4], fmaf(wB.z, h2a[6], wC.x * h2a[8]))));
            float qa = fmaf(wA.y, h2a[1], fmaf(wA.w, h2a[3],
                       fmaf(wB.y, h2a[5], fmaf(wB.w, h2a[7],
                       fmaf(wC.y, h2a[9], bb)))));
            lgl[o] = pa + qa;
            float pb = fmaf(wA.x, h2b[0], fmaf(wA.z, h2b[2],
                       fmaf(wB.x, h2b[4], fmaf(wB.z, h2b[6], wC.x * h2b[8]))));
            float qb = fmaf(wA.y, h2b[1], fmaf(wA.w, h2b[3],
                       fmaf(wB.y, h2b[5], fmaf(wB.w, h2b[7],
                       fmaf(wC.y, h2b[9], bb)))));
            lgh[o] = pb + qb;
        }
        // softmax + CE (per half; one shared mask)
        const float km = m ? invN : 0.f;
        float d00, d01, d02, d10, d11, d12;
        {
            float mm = fmaxf(lgl[0], fmaxf(lgl[1], lgl[2]));
            float e0 = __expf(lgl[0] - mm), e1 = __expf(lgl[1] - mm), e2 = __expf(lgl[2] - mm);
            float sm = e0 + e1 + e2, iv = __fdividef(1.f, sm);
            int y = y01.x;
            float ly = (y == 0) ? lgl[0] : ((y == 1) ? lgl[1] : lgl[2]);
            l0acc += m ? ((mm - ly) + __logf(sm)) : 0.f;
            d00 = (e0 * iv - (y == 0 ? 1.f : 0.f)) * km;
            d01 = (e1 * iv - (y == 1 ? 1.f : 0.f)) * km;
            d02 = (e2 * iv - (y == 2 ? 1.f : 0.f)) * km;
        }
        {
            float mm = fmaxf(lgh[0], fmaxf(lgh[1], lgh[2]));
            float e0 = __expf(lgh[0] - mm), e1 = __expf(lgh[1] - mm), e2 = __expf(lgh[2] - mm);
            float sm = e0 + e1 + e2, iv = __fdividef(1.f, sm);
            int y = y01.y;
            float ly = (y == 0) ? lgh[0] : ((y == 1) ? lgh[1] : lgh[2]);
            l1acc += m ? ((mm - ly) + __logf(sm)) : 0.f;
            d10 = (e0 * iv - (y == 0 ? 1.f : 0.f)) * km;
            d11 = (e1 * iv - (y == 1 ? 1.f : 0.f)) * km;
            d12 = (e2 * iv - (y == 2 ? 1.f : 0.f)) * km;
        }
        *(u64*)&recW[45 * RSC + cj] = pk(d00, d10);
        *(u64*)&recW[50 * RSC + cj] = pk(d01, d11);
        *(u64*)&recW[47 * RSC + cj] = pk(d02, d12);

        // backward: dg rows (relu mask from msk2 bits), dh accumulation
        float dha[10], dhb[10];
#pragma unroll
        for (int h = 0; h < 10; h++) { dha[h] = 0.f; dhb[h] = 0.f; }
#pragma unroll
        for (int g = 0; g < 10; g++) {
            float4 wt = *(const float4*)&P[224 + 4 * g];
            float dga = fmaf(wt.x, d00, fmaf(wt.y, d01, wt.z * d02));
            float dgb = fmaf(wt.x, d10, fmaf(wt.y, d11, wt.z * d12));
            dga = (msk2 & (1u << g))        ? dga : 0.f;
            dgb = (msk2 & (1u << (16 + g))) ? dgb : 0.f;
            *(u64*)&recW[(20 + g) * RSC + cj] = pk(dga, dgb);
            const float* r = &P[52 + 12 * g];
            float4 wA = *(const float4*)r;
            float4 wB = *(const float4*)(r + 4);
            float2 wC = *(const float2*)(r + 8);
            dha[0] = fmaf(wA.x, dga, dha[0]);
            dha[1] = fmaf(wA.y, dga, dha[1]);
            dha[2] = fmaf(wA.z, dga, dha[2]);
            dha[3] = fmaf(wA.w, dga, dha[3]);
            dha[4] = fmaf(wB.x, dga, dha[4]);
            dha[5] = fmaf(wB.y, dga, dha[5]);
            dha[6] = fmaf(wB.z, dga, dha[6]);
            dha[7] = fmaf(wB.w, dga, dha[7]);
            dha[8] = fmaf(wC.x, dga, dha[8]);
            dha[9] = fmaf(wC.y, dga, dha[9]);
            dhb[0] = fmaf(wA.x, dgb, dhb[0]);
            dhb[1] = fmaf(wA.y, dgb, dhb[1]);
            dhb[2] = fmaf(wA.z, dgb, dhb[2]);
            dhb[3] = fmaf(wA.w, dgb, dhb[3]);
            dhb[4] = fmaf(wB.x, dgb, dhb[4]);
            dhb[5] = fmaf(wB.y, dgb, dhb[5]);
            dhb[6] = fmaf(wB.z, dgb, dhb[6]);
            dhb[7] = fmaf(wB.w, dgb, dhb[7]);
            dhb[8] = fmaf(wC.x, dgb, dhb[8]);
            dhb[9] = fmaf(wC.y, dgb, dhb[9]);
        }
        // dhm rows (relu mask from msk1 bits)
#pragma unroll
        for (int h = 0; h < 10; h++) {
            float va = (msk1 & (1u << h))        ? dha[h] : 0.f;
            float vb = (msk1 & (1u << (16 + h))) ? dhb[h] : 0.f;
            *(u64*)&recW[h * RSC + cj] = pk(va, vb);
        }
        __syncwarp();

        // ---- minipass: LDS.128 tiles + free bias sums (packed f32x2) ----
        const int nsteps = (c == 2) ? 6 : 16;   // chunk3: 22 valid samples
#pragma unroll 2
        for (int i = 0; i < nsteps; i++) {
            ulonglong2 a0 = *(const ulonglong2*)&recW[oa0 + 4 * i];
            ulonglong2 a1 = *(const ulonglong2*)&recW[oa1 + 4 * i];
            ulonglong2 b0 = *(const ulonglong2*)&recW[ob0 + 4 * i];
            ulonglong2 b1 = *(const ulonglong2*)&recW[ob1 + 4 * i];
            m0 = ffma2(a0.x, b0.x, m0); m0 = ffma2(a0.y, b0.y, m0);
            m1 = ffma2(a0.x, b1.x, m1); m1 = ffma2(a0.y, b1.y, m1);
            m2 = ffma2(a1.x, b0.x, m2); m2 = ffma2(a1.y, b0.y, m2);
            m3 = ffma2(a1.x, b1.x, m3); m3 = ffma2(a1.y, b1.y, m3);
            sa0 = add2(sa0, add2(a0.x, a0.y));
            sa1 = add2(sa1, add2(a1.x, a1.y));
            ulonglong2 e0 = *(const ulonglong2*)&recW[oe0 + 4 * i];
            ulonglong2 e1 = *(const ulonglong2*)&recW[oe1 + 4 * i];
            ulonglong2 f0 = *(const ulonglong2*)&recW[of0 + 4 * i];
            ulonglong2 f1 = *(const ulonglong2*)&recW[of1 + 4 * i];
            m4 = ffma2(e0.x, f0.x, m4); m4 = ffma2(e0.y, f0.y, m4);
            m5 = ffma2(e0.x, f1.x, m5); m5 = ffma2(e0.y, f1.y, m5);
            m6 = ffma2(e1.x, f0.x, m6); m6 = ffma2(e1.y, f0.y, m6);
            m7 = ffma2(e1.x, f1.x, m7); m7 = ffma2(e1.y, f1.y, m7);
            se0 = add2(se0, add2(e0.x, e0.y));
            se1 = add2(se1, add2(e1.x, e1.y));
        }
        __syncwarp();   // before next chunk overwrites rec rows
    }

    // ---- finalize grads, sumsq ----
    float ssq = 0.f;
    float* gout = wout + 193;
    float lo, hi, v;
#define EMIT(ACC, IDX) do { upk(ACC, lo, hi); v = lo + hi; \
        gout[(IDX)] = v; ssq = fmaf(v, v, ssq); } while (0)
    if (lane < 25) {
        int q = lane / 5, r = lane % 5;
        EMIT(m0, 50 + 10 * q + r);
        EMIT(m1, 55 + 10 * q + r);
        EMIT(m2, 100 + 10 * q + r);
        EMIT(m3, 105 + 10 * q + r);
        if (r == 0) { EMIT(sa0, 150 + q); EMIT(sa1, 155 + q); }
    }
    if (lane < 10) {
        int a = lane >> 1, bq = lane & 1;
        int bs = 4 * a + 2 * bq;
        EMIT(m4, bs); EMIT(m5, bs + 1); EMIT(m6, bs + 20); EMIT(m7, bs + 21);
        if (bq == 0) { EMIT(se0, 40 + a); EMIT(se1, 45 + a); }
    } else if (lane < 20) {
        int l = lane - 10, p = l / 5, qh = l % 5;
        if (p == 0) {
            EMIT(m4, 160 + qh); EMIT(m5, 165 + qh);
            EMIT(m6, 170 + qh); EMIT(m7, 175 + qh);
            if (qh == 0) { EMIT(se0, 190); EMIT(se1, 191); }
        } else {
            EMIT(m4, 180 + qh); EMIT(m5, 185 + qh);
            if (qh == 0) { EMIT(se0, 192); }
        }
    }
#undef EMIT

    float lossacc = l0acc + l1acc;
    lossacc += __shfl_xor_sync(0xffffffffu, lossacc, 16);
    lossacc += __shfl_xor_sync(0xffffffffu, lossacc, 8);
    lossacc += __shfl_xor_sync(0xffffffffu, lossacc, 4);
    lossacc += __shfl_xor_sync(0xffffffffu, lossacc, 2);
    lossacc += __shfl_xor_sync(0xffffffffu, lossacc, 1);
    const float loss_b = lossacc * invN;

    ssq += __shfl_xor_sync(0xffffffffu, ssq, 16);
    ssq += __shfl_xor_sync(0xffffffffu, ssq, 8);
    ssq += __shfl_xor_sync(0xffffffffu, ssq, 4);
    ssq += __shfl_xor_sync(0xffffffffu, ssq, 2);
    ssq += __shfl_xor_sync(0xffffffffu, ssq, 1);

    if (lane == 0) {
        atomicAdd(&g_sumsq, ssq);
        wout[386] = loss_b;
        wout[387] = clip1e4(fv[b] - loss_b);
    }
}

// Apply global grad-norm clip coefficient to the grad columns [193, 386).
__global__ void k_scale(float* __restrict__ out) {
    const float coef = fminf(1.f, 10.f / (sqrtf(g_sumsq) + 1e-6f));
    const int b = blockIdx.x;
    const int k = threadIdx.x;
    if (k < 193) {
        size_t idx = (size_t)b * 388 + 193 + k;
        out[idx] *= coef;
    }
}

extern "C" void kernel_launch(void* const* d_in, const int* in_sizes, int n_in,
                              void* d_out, int out_size)
{
    const float* W1 = (const float*)d_in[0];
    const float* b1 = (const float*)d_in[1];
    const float* W2 = (const float*)d_in[2];
    const float* b2 = (const float*)d_in[3];
    const float* W3 = (const float*)d_in[4];
    const float* b3 = (const float*)d_in[5];
    const float* G1 = (const float*)d_in[6];
    const float* G2 = (const float*)d_in[7];
    const float* G3 = (const float*)d_in[8];
    const float* G4 = (const float*)d_in[9];
    const float* G5 = (const float*)d_in[10];
    const float* G6 = (const float*)d_in[11];
    const float* dx = (const float*)d_in[12];
    const float* fv = (const float*)d_in[13];
    const int*   dy = (const int*)d_in[14];
    const int*   ss = (const int*)d_in[15];
    float* out = (float*)d_out;

    const int B = in_sizes[13];   // func_val is [B]

    static int carveout_set = 0;
    if (!carveout_set) {
        cudaFuncSetAttribute(k_main,
                             cudaFuncAttributePreferredSharedMemoryCarveout,
                             cudaSharedmemCarveoutMaxShared);
        carveout_set = 1;
    }

    // g_sumsq is 0 on entry: static init on first call, k_zero (below) after.
    k_main<<<B / WPB, BDIM>>>(W1, b1, W2, b2, W3, b3,
                              G1, G2, G3, G4, G5, G6,
                              dx, fv, dy, ss, out);
    k_scale<<<B, 224>>>(out);
    k_zero<<<1, 1>>>();          // reset for the next (graph-replayed) call
}

// round 15
// speedup vs baseline: 1.1146x; 1.1146x over previous
#include <cuda_runtime.h>

#define BDIM 64
#define WPB 2             // warps (MLPs) per block
#define RSC 68            // rec row stride; mult of 4 (16B align), ==4 mod 32
#define NROWS 51
#define RECW (NROWS * RSC)
#define PSTRIDE 264
#define NS 150

typedef unsigned long long u64;

__constant__ float c_lr[6] = {0.001f, 0.01f, 0.05f, 0.1f, 0.5f, 1.0f};
__device__ float g_sumsq = 0.f;   // zeroed by k_zero at END of each call

__device__ __forceinline__ float clip1e4(float v) {
    return fminf(fmaxf(v, -10000.f), 10000.f);
}
__device__ __forceinline__ u64 pk(float lo, float hi) {
    u64 r; asm("mov.b64 %0, {%1,%2};" : "=l"(r) : "f"(lo), "f"(hi)); return r;
}
__device__ __forceinline__ void upk(u64 v, float& lo, float& hi) {
    asm("mov.b64 {%0,%1}, %2;" : "=f"(lo), "=f"(hi) : "l"(v));
}
__device__ __forceinline__ u64 ffma2(u64 a, u64 b, u64 c) {
    u64 d; asm("fma.rn.f32x2 %0, %1, %2, %3;" : "=l"(d) : "l"(a), "l"(b), "l"(c));
    return d;
}
__device__ __forceinline__ u64 add2(u64 a, u64 b) {
    u64 d; asm("add.rn.f32x2 %0, %1, %2;" : "=l"(d) : "l"(a), "l"(b)); return d;
}

__global__ void k_zero() { g_sumsq = 0.f; }

// rec row map (per warp):
//  0..9  dhm    10..19 h1    20..29 dg    30..39 h2
//  43 x0  48 x1  44 x2  49 x3     45 d0  50 d1  47 d2
__global__ void __launch_bounds__(BDIM, 6) k_main(
    const float* __restrict__ W1, const float* __restrict__ b1,
    const float* __restrict__ W2, const float* __restrict__ b2,
    const float* __restrict__ W3, const float* __restrict__ b3,
    const float* __restrict__ G1, const float* __restrict__ G2,
    const float* __restrict__ G3, const float* __restrict__ G4,
    const float* __restrict__ G5, const float* __restrict__ G6,
    const float* __restrict__ dx, const float* __restrict__ fv,
    const int* __restrict__ dy, const int* __restrict__ ss,
    float* __restrict__ out)
{
    __shared__ __align__(16) float ps[WPB * PSTRIDE];
    __shared__ __align__(16) float rec[WPB * RECW];

    const int tid  = threadIdx.x;
    const int lane = tid & 31;
    const int warp = tid >> 5;
    const int b    = blockIdx.x * WPB + warp;

    float* P    = ps  + warp * PSTRIDE;
    float* recW = rec + warp * RECW;
    // P layout: 0:W1[10x4] 40:b1[10] 52:W2 rows stride 12 (10 rows)
    // 172:b2[10] 184:W3 rows stride 12 (3 rows) 220:b3[3] 224:W3^T stride 4

    const float lr = c_lr[ss[b]];
    float* wout = out + (size_t)b * 388;

    for (int k = lane; k < PSTRIDE; k += 32) P[k] = 0.f;
    __syncwarp();
    for (int k = lane; k < 40; k += 32) {
        float p = fmaf(-lr, G1[b * 40 + k], W1[b * 40 + k]);
        P[k] = p; wout[k] = clip1e4(p);
    }
    for (int k = lane; k < 10; k += 32) {
        float p = fmaf(-lr, G2[b * 10 + k], b1[b * 10 + k]);
        P[40 + k] = p; wout[40 + k] = clip1e4(p);
    }
    for (int k = lane; k < 100; k += 32) {
        float p = fmaf(-lr, G3[b * 100 + k], W2[b * 100 + k]);
        int r = k / 10, c = k - r * 10;
        P[52 + 12 * r + c] = p; wout[50 + k] = clip1e4(p);
    }
    for (int k = lane; k < 10; k += 32) {
        float p = fmaf(-lr, G4[b * 10 + k], b2[b * 10 + k]);
        P[172 + k] = p; wout[150 + k] = clip1e4(p);
    }
    for (int k = lane; k < 30; k += 32) {
        float p = fmaf(-lr, G5[b * 30 + k], W3[b * 30 + k]);
        int r = k / 10, c = k - r * 10;
        P[184 + 12 * r + c] = p;
        P[224 + 4 * c + r]  = p;                 // W3^T (rows stride 4)
        wout[160 + k] = clip1e4(p);
    }
    for (int k = lane; k < 3; k += 32) {
        float p = fmaf(-lr, G6[b * 3 + k], b3[b * 3 + k]);
        P[220 + k] = p; wout[190 + k] = clip1e4(p);
    }
    __syncwarp();

    // ---- minipass offsets (floats from recW), bank-planned ----
    int oa0, oa1, ob0, ob1;                 // tile-set 1: gW2 5x5 pair tiles
    {
        int q = (lane < 25) ? lane / 5 : 0;
        int r = (lane < 25) ? lane % 5 : 0;
        oa0 = (20 + q) * RSC; oa1 = (25 + q) * RSC;   // dg rows (A)
        ob0 = (10 + r) * RSC; ob1 = (15 + r) * RSC;   // h1 rows (B)
    }
    int oe0, oe1, of0, of1;                 // tile-set 2: gW1 / gW3
    if (lane < 10) {
        int a = lane >> 1, bq = lane & 1;
        oe0 = a * RSC; oe1 = (a + 5) * RSC;                  // dhm rows
        of0 = (bq ? 44 : 43) * RSC; of1 = (bq ? 49 : 48) * RSC; // x rows
    } else if (lane < 20) {
        int l = lane - 10, p = l / 5, qh = l % 5;
        oe0 = (p ? 47 : 45) * RSC; oe1 = 50 * RSC;           // d rows
        of0 = (30 + qh) * RSC; of1 = (35 + qh) * RSC;        // h2 rows
    } else {
        oe0 = 0; oe1 = 5 * RSC; of0 = 43 * RSC; of1 = 48 * RSC; // dummies
    }

    u64 m0 = 0ull, m1 = 0ull, m2 = 0ull, m3 = 0ull;
    u64 m4 = 0ull, m5 = 0ull, m6 = 0ull, m7 = 0ull;
    u64 sa0 = 0ull, sa1 = 0ull, se0 = 0ull, se1 = 0ull;   // bias sums

    float l0acc = 0.f, l1acc = 0.f;
    const float invN = 1.f / 150.f;
    const int cj = 2 * lane;

#pragma unroll 1
    for (int c = 0; c < 3; c++) {
        const int s0 = 64 * c + cj;
        const bool m = (s0 < NS);           // NS even, s0 even -> one mask
        float4 xa = make_float4(0.f, 0.f, 0.f, 0.f);
        float4 xb = xa;
        int2 y01 = make_int2(0, 0);
        if (m) {
            xa = ((const float4*)dx)[s0];
            xb = ((const float4*)dx)[s0 + 1];
            y01 = *(const int2*)&dy[s0];
        }
        *(u64*)&recW[43 * RSC + cj] = pk(xa.x, xb.x);
        *(u64*)&recW[48 * RSC + cj] = pk(xa.y, xb.y);
        *(u64*)&recW[44 * RSC + cj] = pk(xa.z, xb.z);
        *(u64*)&recW[49 * RSC + cj] = pk(xa.w, xb.w);

        // layer 1 (scalar, two samples, bias folded into chain head)
        // relu mask packed: bit h = sample a, bit 16+h = sample b
        float h1a[10], h1b[10];
        unsigned msk1 = 0u;
#pragma unroll
        for (int h = 0; h < 10; h++) {
            float4 w = *(const float4*)&P[4 * h];
            float bb = P[40 + h];
            float pa = fmaf(w.x, xa.x, fmaf(w.y, xa.y, bb));
            float qa = fmaf(w.z, xa.z, w.w * xa.w);
            float va = fmaxf(pa + qa, 0.f);
            float pb = fmaf(w.x, xb.x, fmaf(w.y, xb.y, bb));
            float qb = fmaf(w.z, xb.z, w.w * xb.w);
            float vb = fmaxf(pb + qb, 0.f);
            msk1 |= (va > 0.f) ? (1u << h) : 0u;
            msk1 |= (vb > 0.f) ? (1u << (16 + h)) : 0u;
            h1a[h] = va; h1b[h] = vb;
            *(u64*)&recW[(10 + h) * RSC + cj] = pk(va, vb);
        }
        // layer 2 (scalar; h1 arrays die here)
        float h2a[10], h2b[10];
        unsigned msk2 = 0u;
#pragma unroll
        for (int g = 0; g < 10; g++) {
            const float* r = &P[52 + 12 * g];
            float4 wA = *(const float4*)r;
            float4 wB = *(const float4*)(r + 4);
            float2 wC = *(const float2*)(r + 8);
            float bb = P[172 + g];
            float pa = fmaf(wA.x, h1a[0], fmaf(wA.z, h1a[2],
                       fmaf(wB.x, h1a[4], fmaf(wB.z, h1a[6], wC.x * h1a[8]))));
            float qa = fmaf(wA.y, h1a[1], fmaf(wA.w, h1a[3],
                       fmaf(wB.y, h1a[5], fmaf(wB.w, h1a[7],
                       fmaf(wC.y, h1a[9], bb)))));
            float va = fmaxf(pa + qa, 0.f);
            float pb = fmaf(wA.x, h1b[0], fmaf(wA.z, h1b[2],
                       fmaf(wB.x, h1b[4], fmaf(wB.z, h1b[6], wC.x * h1b[8]))));
            float qb = fmaf(wA.y, h1b[1], fmaf(wA.w, h1b[3],
                       fmaf(wB.y, h1b[5], fmaf(wB.w, h1b[7],
                       fmaf(wC.y, h1b[9], bb)))));
            float vb = fmaxf(pb + qb, 0.f);
            msk2 |= (va > 0.f) ? (1u << g) : 0u;
            msk2 |= (vb > 0.f) ? (1u << (16 + g)) : 0u;
            h2a[g] = va; h2b[g] = vb;
            *(u64*)&recW[(30 + g) * RSC + cj] = pk(va, vb);
        }
        // layer 3 logits (scalar; h2 arrays die here)
        float lgl[3], lgh[3];
#pragma unroll
        for (int o = 0; o < 3; o++) {
            const float* r = &P[184 + 12 * o];
            float4 wA = *(const float4*)r;
            float4 wB = *(const float4*)(r + 4);
            float2 wC = *(const float2*)(r + 8);
            float bb = P[220 + o];
            float pa = fmaf(wA.x, h2a[0], fmaf(wA.z, h2a[2],
                       fmaf(wB.x, h2a[4], fmaf(wB.z, h2a[6], wC.x * h2a[8]))));
            float qa = fmaf(wA.y, h2a[1], fmaf(wA.w, h2a[3],
                       fmaf(wB.y, h2a[5], fmaf(wB.w, h2a[7],
                       fmaf(wC.y, h2a[9], bb)))));
            lgl[o] = pa + qa;
            float pb = fmaf(wA.x, h2b[0], fmaf(wA.z, h2b[2],
                       fmaf(wB.x, h2b[4], fmaf(wB.z, h2b[6], wC.x * h2b[8]))));
            float qb = fmaf(wA.y, h2b[1], fmaf(wA.w, h2b[3],
                       fmaf(wB.y, h2b[5], fmaf(wB.w, h2b[7],
                       fmaf(wC.y, h2b[9], bb)))));
            lgh[o] = pb + qb;
        }
        // softmax + CE (per half; one shared mask)
        const float km = m ? invN : 0.f;
        float d00, d01, d02, d10, d11, d12;
        {
            float mm = fmaxf(lgl[0], fmaxf(lgl[1], lgl[2]));
            float e0 = __expf(lgl[0] - mm), e1 = __expf(lgl[1] - mm), e2 = __expf(lgl[2] - mm);
            float sm = e0 + e1 + e2, iv = __fdividef(1.f, sm);
            int y = y01.x;
            float ly = (y == 0) ? lgl[0] : ((y == 1) ? lgl[1] : lgl[2]);
            l0acc += m ? ((mm - ly) + __logf(sm)) : 0.f;
            d00 = (e0 * iv - (y == 0 ? 1.f : 0.f)) * km;
            d01 = (e1 * iv - (y == 1 ? 1.f : 0.f)) * km;
            d02 = (e2 * iv - (y == 2 ? 1.f : 0.f)) * km;
        }
        {
            float mm = fmaxf(lgh[0], fmaxf(lgh[1], lgh[2]));
            float e0 = __expf(lgh[0] - mm), e1 = __expf(lgh[1] - mm), e2 = __expf(lgh[2] - mm);
            float sm = e0 + e1 + e2, iv = __fdividef(1.f, sm);
            int y = y01.y;
            float ly = (y == 0) ? lgh[0] : ((y == 1) ? lgh[1] : lgh[2]);
            l1acc += m ? ((mm - ly) + __logf(sm)) : 0.f;
            d10 = (e0 * iv - (y == 0 ? 1.f : 0.f)) * km;
            d11 = (e1 * iv - (y == 1 ? 1.f : 0.f)) * km;
            d12 = (e2 * iv - (y == 2 ? 1.f : 0.f)) * km;
        }
        *(u64*)&recW[45 * RSC + cj] = pk(d00, d10);
        *(u64*)&recW[50 * RSC + cj] = pk(d01, d11);
        *(u64*)&recW[47 * RSC + cj] = pk(d02, d12);

        // backward: dg rows (relu mask from msk2 bits), dh accumulation
        float dha[10], dhb[10];
#pragma unroll
        for (int h = 0; h < 10; h++) { dha[h] = 0.f; dhb[h] = 0.f; }
#pragma unroll
        for (int g = 0; g < 10; g++) {
            float4 wt = *(const float4*)&P[224 + 4 * g];
            float dga = fmaf(wt.x, d00, fmaf(wt.y, d01, wt.z * d02));
            float dgb = fmaf(wt.x, d10, fmaf(wt.y, d11, wt.z * d12));
            dga = (msk2 & (1u << g))        ? dga : 0.f;
            dgb = (msk2 & (1u << (16 + g))) ? dgb : 0.f;
            *(u64*)&recW[(20 + g) * RSC + cj] = pk(dga, dgb);
            const float* r = &P[52 + 12 * g];
            float4 wA = *(const float4*)r;
            float4 wB = *(const float4*)(r + 4);
            float2 wC = *(const float2*)(r + 8);
            dha[0] = fmaf(wA.x, dga, dha[0]);
            dha[1] = fmaf(wA.y, dga, dha[1]);
            dha[2] = fmaf(wA.z, dga, dha[2]);
            dha[3] = fmaf(wA.w, dga, dha[3]);
            dha[4] = fmaf(wB.x, dga, dha[4]);
            dha[5] = fmaf(wB.y, dga, dha[5]);
            dha[6] = fmaf(wB.z, dga, dha[6]);
            dha[7] = fmaf(wB.w, dga, dha[7]);
            dha[8] = fmaf(wC.x, dga, dha[8]);
            dha[9] = fmaf(wC.y, dga, dha[9]);
            dhb[0] = fmaf(wA.x, dgb, dhb[0]);
            dhb[1] = fmaf(wA.y, dgb, dhb[1]);
            dhb[2] = fmaf(wA.z, dgb, dhb[2]);
            dhb[3] = fmaf(wA.w, dgb, dhb[3]);
            dhb[4] = fmaf(wB.x, dgb, dhb[4]);
            dhb[5] = fmaf(wB.y, dgb, dhb[5]);
            dhb[6] = fmaf(wB.z, dgb, dhb[6]);
            dhb[7] = fmaf(wB.w, dgb, dhb[7]);
            dhb[8] = fmaf(wC.x, dgb, dhb[8]);
            dhb[9] = fmaf(wC.y, dgb, dhb[9]);
        }
        // dhm rows (relu mask from msk1 bits)
#pragma unroll
        for (int h = 0; h < 10; h++) {
            float va = (msk1 & (1u << h))        ? dha[h] : 0.f;
            float vb = (msk1 & (1u << (16 + h))) ? dhb[h] : 0.f;
            *(u64*)&recW[h * RSC + cj] = pk(va, vb);
        }
        __syncwarp();

        // ---- minipass: LDS.128 tiles + free bias sums (packed f32x2) ----
        const int nsteps = (c == 2) ? 6 : 16;   // chunk3: 22 valid samples
#pragma unroll 2
        for (int i = 0; i < nsteps; i++) {
            ulonglong2 a0 = *(const ulonglong2*)&recW[oa0 + 4 * i];
            ulonglong2 a1 = *(const ulonglong2*)&recW[oa1 + 4 * i];
            ulonglong2 b0 = *(const ulonglong2*)&recW[ob0 + 4 * i];
            ulonglong2 b1 = *(const ulonglong2*)&recW[ob1 + 4 * i];
            m0 = ffma2(a0.x, b0.x, m0); m0 = ffma2(a0.y, b0.y, m0);
            m1 = ffma2(a0.x, b1.x, m1); m1 = ffma2(a0.y, b1.y, m1);
            m2 = ffma2(a1.x, b0.x, m2); m2 = ffma2(a1.y, b0.y, m2);
            m3 = ffma2(a1.x, b1.x, m3); m3 = ffma2(a1.y, b1.y, m3);
            sa0 = add2(sa0, add2(a0.x, a0.y));
            sa1 = add2(sa1, add2(a1.x, a1.y));
            ulonglong2 e0 = *(const ulonglong2*)&recW[oe0 + 4 * i];
            ulonglong2 e1 = *(const ulonglong2*)&recW[oe1 + 4 * i];
            ulonglong2 f0 = *(const ulonglong2*)&recW[of0 + 4 * i];
            ulonglong2 f1 = *(const ulonglong2*)&recW[of1 + 4 * i];
            m4 = ffma2(e0.x, f0.x, m4); m4 = ffma2(e0.y, f0.y, m4);
            m5 = ffma2(e0.x, f1.x, m5); m5 = ffma2(e0.y, f1.y, m5);
            m6 = ffma2(e1.x, f0.x, m6); m6 = ffma2(e1.y, f0.y, m6);
            m7 = ffma2(e1.x, f1.x, m7); m7 = ffma2(e1.y, f1.y, m7);
            se0 = add2(se0, add2(e0.x, e0.y));
            se1 = add2(se1, add2(e1.x, e1.y));
        }
        __syncwarp();   // before next chunk overwrites rec rows
    }

    // ---- finalize grads, sumsq ----
    float ssq = 0.f;
    float* gout = wout + 193;
    float lo, hi, v;
#define EMIT(ACC, IDX) do { upk(ACC, lo, hi); v = lo + hi; \
        gout[(IDX)] = v; ssq = fmaf(v, v, ssq); } while (0)
    if (lane < 25) {
        int q = lane / 5, r = lane % 5;
        EMIT(m0, 50 + 10 * q + r);
        EMIT(m1, 55 + 10 * q + r);
        EMIT(m2, 100 + 10 * q + r);
        EMIT(m3, 105 + 10 * q + r);
        if (r == 0) { EMIT(sa0, 150 + q); EMIT(sa1, 155 + q); }
    }
    if (lane < 10) {
        int a = lane >> 1, bq = lane & 1;
        int bs = 4 * a + 2 * bq;
        EMIT(m4, bs); EMIT(m5, bs + 1); EMIT(m6, bs + 20); EMIT(m7, bs + 21);
        if (bq == 0) { EMIT(se0, 40 + a); EMIT(se1, 45 + a); }
    } else if (lane < 20) {
        int l = lane - 10, p = l / 5, qh = l % 5;
        if (p == 0) {
            EMIT(m4, 160 + qh); EMIT(m5, 165 + qh);
            EMIT(m6, 170 + qh); EMIT(m7, 175 + qh);
            if (qh == 0) { EMIT(se0, 190); EMIT(se1, 191); }
        } else {
            EMIT(m4, 180 + qh); EMIT(m5, 185 + qh);
            if (qh == 0) { EMIT(se0, 192); }
        }
    }
#undef EMIT

    float lossacc = l0acc + l1acc;
    lossacc += __shfl_xor_sync(0xffffffffu, lossacc, 16);
    lossacc += __shfl_xor_sync(0xffffffffu, lossacc, 8);
    lossacc += __shfl_xor_sync(0xffffffffu, lossacc, 4);
    lossacc += __shfl_xor_sync(0xffffffffu, lossacc, 2);
    lossacc += __shfl_xor_sync(0xffffffffu, lossacc, 1);
    const float loss_b = lossacc * invN;

    ssq += __shfl_xor_sync(0xffffffffu, ssq, 16);
    ssq += __shfl_xor_sync(0xffffffffu, ssq, 8);
    ssq += __shfl_xor_sync(0xffffffffu, ssq, 4);
    ssq += __shfl_xor_sync(0xffffffffu, ssq, 2);
    ssq += __shfl_xor_sync(0xffffffffu, ssq, 1);

    if (lane == 0) {
        atomicAdd(&g_sumsq, ssq);
        wout[386] = loss_b;
        wout[387] = clip1e4(fv[b] - loss_b);
    }
}

// Apply global grad-norm clip coefficient to the grad columns [193, 386).
__global__ void k_scale(float* __restrict__ out) {
    const float coef = fminf(1.f, 10.f / (sqrtf(g_sumsq) + 1e-6f));
    const int b = blockIdx.x;
    const int k = threadIdx.x;
    if (k < 193) {
        size_t idx = (size_t)b * 388 + 193 + k;
        out[idx] *= coef;
    }
}

extern "C" void kernel_launch(void* const* d_in, const int* in_sizes, int n_in,
                              void* d_out, int out_size)
{
    const float* W1 = (const float*)d_in[0];
    const float* b1 = (const float*)d_in[1];
    const float* W2 = (const float*)d_in[2];
    const float* b2 = (const float*)d_in[3];
    const float* W3 = (const float*)d_in[4];
    const float* b3 = (const float*)d_in[5];
    const float* G1 = (const float*)d_in[6];
    const float* G2 = (const float*)d_in[7];
    const float* G3 = (const float*)d_in[8];
    const float* G4 = (const float*)d_in[9];
    const float* G5 = (const float*)d_in[10];
    const float* G6 = (const float*)d_in[11];
    const float* dx = (const float*)d_in[12];
    const float* fv = (const float*)d_in[13];
    const int*   dy = (const int*)d_in[14];
    const int*   ss = (const int*)d_in[15];
    float* out = (float*)d_out;

    const int B = in_sizes[13];   // func_val is [B]

    static int carveout_set = 0;
    if (!carveout_set) {
        cudaFuncSetAttribute(k_main,
                             cudaFuncAttributePreferredSharedMemoryCarveout,
                             cudaSharedmemCarveoutMaxShared);
        carveout_set = 1;
    }

    // g_sumsq is 0 on entry: static init on first call, k_zero (below) after.
    k_main<<<B / WPB, BDIM>>>(W1, b1, W2, b2, W3, b3,
                              G1, G2, G3, G4, G5, G6,
                              dx, fv, dy, ss, out);
    k_scale<<<B, 224>>>(out);
    k_zero<<<1, 1>>>();          // reset for the next (graph-replayed) call
}

// round 16
// speedup vs baseline: 1.3119x; 1.1770x over previous
#include <cuda_runtime.h>

#define BDIM 64
#define WPB 2             // warps (MLPs) per block
#define RSC 68            // rec row stride; mult of 4 (16B align), ==4 mod 32
#define NROWS 51
#define RECW (NROWS * RSC)
#define PSTRIDE 264
#define NS 150

typedef unsigned long long u64;

__constant__ float c_lr[6] = {0.001f, 0.01f, 0.05f, 0.1f, 0.5f, 1.0f};
__device__ float g_sumsq = 0.f;   // zeroed by k_zero at END of each call

__device__ __forceinline__ float clip1e4(float v) {
    return fminf(fmaxf(v, -10000.f), 10000.f);
}
__device__ __forceinline__ u64 pk(float lo, float hi) {
    u64 r; asm("mov.b64 %0, {%1,%2};" : "=l"(r) : "f"(lo), "f"(hi)); return r;
}
__device__ __forceinline__ void upk(u64 v, float& lo, float& hi) {
    asm("mov.b64 {%0,%1}, %2;" : "=f"(lo), "=f"(hi) : "l"(v));
}
__device__ __forceinline__ u64 ffma2(u64 a, u64 b, u64 c) {
    u64 d; asm("fma.rn.f32x2 %0, %1, %2, %3;" : "=l"(d) : "l"(a), "l"(b), "l"(c));
    return d;
}
__device__ __forceinline__ u64 add2(u64 a, u64 b) {
    u64 d; asm("add.rn.f32x2 %0, %1, %2;" : "=l"(d) : "l"(a), "l"(b)); return d;
}

__global__ void k_zero() { g_sumsq = 0.f; }

// rec row map (per warp):
//  0..9  dhm    10..19 h1    20..29 dg    30..39 h2
//  43 x0  48 x1  44 x2  49 x3     45 d0  50 d1  47 d2
__global__ void __launch_bounds__(BDIM, 6) k_main(
    const float* __restrict__ W1, const float* __restrict__ b1,
    const float* __restrict__ W2, const float* __restrict__ b2,
    const float* __restrict__ W3, const float* __restrict__ b3,
    const float* __restrict__ G1, const float* __restrict__ G2,
    const float* __restrict__ G3, const float* __restrict__ G4,
    const float* __restrict__ G5, const float* __restrict__ G6,
    const float* __restrict__ dx, const float* __restrict__ fv,
    const int* __restrict__ dy, const int* __restrict__ ss,
    float* __restrict__ out)
{
    __shared__ __align__(16) float ps[WPB * PSTRIDE];
    __shared__ __align__(16) float rec[WPB * RECW];

    const int tid  = threadIdx.x;
    const int lane = tid & 31;
    const int warp = tid >> 5;
    const int b    = blockIdx.x * WPB + warp;

    float* P    = ps  + warp * PSTRIDE;
    float* recW = rec + warp * RECW;
    // P layout: 0:W1[10x4] 40:b1[10] 52:W2 rows stride 12 (10 rows)
    // 172:b2[10] 184:W3 rows stride 12 (3 rows) 220:b3[3] 224:W3^T stride 4

    const float lr = c_lr[ss[b]];
    float* wout = out + (size_t)b * 388;

    for (int k = lane; k < PSTRIDE; k += 32) P[k] = 0.f;
    __syncwarp();
    for (int k = lane; k < 40; k += 32) {
        float p = fmaf(-lr, G1[b * 40 + k], W1[b * 40 + k]);
        P[k] = p; wout[k] = clip1e4(p);
    }
    for (int k = lane; k < 10; k += 32) {
        float p = fmaf(-lr, G2[b * 10 + k], b1[b * 10 + k]);
        P[40 + k] = p; wout[40 + k] = clip1e4(p);
    }
    for (int k = lane; k < 100; k += 32) {
        float p = fmaf(-lr, G3[b * 100 + k], W2[b * 100 + k]);
        int r = k / 10, c = k - r * 10;
        P[52 + 12 * r + c] = p; wout[50 + k] = clip1e4(p);
    }
    for (int k = lane; k < 10; k += 32) {
        float p = fmaf(-lr, G4[b * 10 + k], b2[b * 10 + k]);
        P[172 + k] = p; wout[150 + k] = clip1e4(p);
    }
    for (int k = lane; k < 30; k += 32) {
        float p = fmaf(-lr, G5[b * 30 + k], W3[b * 30 + k]);
        int r = k / 10, c = k - r * 10;
        P[184 + 12 * r + c] = p;
        P[224 + 4 * c + r]  = p;                 // W3^T (rows stride 4)
        wout[160 + k] = clip1e4(p);
    }
    for (int k = lane; k < 3; k += 32) {
        float p = fmaf(-lr, G6[b * 3 + k], b3[b * 3 + k]);
        P[220 + k] = p; wout[190 + k] = clip1e4(p);
    }
    __syncwarp();

    // ---- minipass offsets (floats from recW), bank-planned ----
    int oa0, oa1, ob0, ob1;                 // tile-set 1: gW2 5x5 pair tiles
    {
        int q = (lane < 25) ? lane / 5 : 0;
        int r = (lane < 25) ? lane % 5 : 0;
        oa0 = (20 + q) * RSC; oa1 = (25 + q) * RSC;   // dg rows (A)
        ob0 = (10 + r) * RSC; ob1 = (15 + r) * RSC;   // h1 rows (B)
    }
    int oe0, oe1, of0, of1;                 // tile-set 2: gW1 / gW3
    if (lane < 10) {
        int a = lane >> 1, bq = lane & 1;
        oe0 = a * RSC; oe1 = (a + 5) * RSC;                  // dhm rows
        of0 = (bq ? 44 : 43) * RSC; of1 = (bq ? 49 : 48) * RSC; // x rows
    } else if (lane < 20) {
        int l = lane - 10, p = l / 5, qh = l % 5;
        oe0 = (p ? 47 : 45) * RSC; oe1 = 50 * RSC;           // d rows
        of0 = (30 + qh) * RSC; of1 = (35 + qh) * RSC;        // h2 rows
    } else {
        oe0 = 0; oe1 = 5 * RSC; of0 = 43 * RSC; of1 = 48 * RSC; // dummies
    }

    u64 m0 = 0ull, m1 = 0ull, m2 = 0ull, m3 = 0ull;
    u64 m4 = 0ull, m5 = 0ull, m6 = 0ull, m7 = 0ull;
    u64 sa0 = 0ull, sa1 = 0ull, se0 = 0ull, se1 = 0ull;   // bias sums

    float l0acc = 0.f, l1acc = 0.f;
    const float invN = 1.f / 150.f;
    const int cj = 2 * lane;

    // ================= chunks 0,1: full pair bodies, no masking =============
#pragma unroll 1
    for (int c = 0; c < 2; c++) {
        const int s0 = 64 * c + cj;           // <= 126, always valid
        float4 xa = ((const float4*)dx)[s0];
        float4 xb = ((const float4*)dx)[s0 + 1];
        int2 y01 = *(const int2*)&dy[s0];
        *(u64*)&recW[43 * RSC + cj] = pk(xa.x, xb.x);
        *(u64*)&recW[48 * RSC + cj] = pk(xa.y, xb.y);
        *(u64*)&recW[44 * RSC + cj] = pk(xa.z, xb.z);
        *(u64*)&recW[49 * RSC + cj] = pk(xa.w, xb.w);

        // layer 1
        float h1a[10], h1b[10];
#pragma unroll
        for (int h = 0; h < 10; h++) {
            float4 w = *(const float4*)&P[4 * h];
            float bb = P[40 + h];
            float pa = fmaf(w.x, xa.x, fmaf(w.y, xa.y, bb));
            float qa = fmaf(w.z, xa.z, w.w * xa.w);
            float va = fmaxf(pa + qa, 0.f);
            float pb = fmaf(w.x, xb.x, fmaf(w.y, xb.y, bb));
            float qb = fmaf(w.z, xb.z, w.w * xb.w);
            float vb = fmaxf(pb + qb, 0.f);
            h1a[h] = va; h1b[h] = vb;
            *(u64*)&recW[(10 + h) * RSC + cj] = pk(va, vb);
        }
        // layer 2
        float h2a[10], h2b[10];
#pragma unroll
        for (int g = 0; g < 10; g++) {
            const float* r = &P[52 + 12 * g];
            float4 wA = *(const float4*)r;
            float4 wB = *(const float4*)(r + 4);
            float2 wC = *(const float2*)(r + 8);
            float bb = P[172 + g];
            float pa = fmaf(wA.x, h1a[0], fmaf(wA.z, h1a[2],
                       fmaf(wB.x, h1a[4], fmaf(wB.z, h1a[6], wC.x * h1a[8]))));
            float qa = fmaf(wA.y, h1a[1], fmaf(wA.w, h1a[3],
                       fmaf(wB.y, h1a[5], fmaf(wB.w, h1a[7],
                       fmaf(wC.y, h1a[9], bb)))));
            float va = fmaxf(pa + qa, 0.f);
            float pb = fmaf(wA.x, h1b[0], fmaf(wA.z, h1b[2],
                       fmaf(wB.x, h1b[4], fmaf(wB.z, h1b[6], wC.x * h1b[8]))));
            float qb = fmaf(wA.y, h1b[1], fmaf(wA.w, h1b[3],
                       fmaf(wB.y, h1b[5], fmaf(wB.w, h1b[7],
                       fmaf(wC.y, h1b[9], bb)))));
            float vb = fmaxf(pb + qb, 0.f);
            h2a[g] = va; h2b[g] = vb;
            *(u64*)&recW[(30 + g) * RSC + cj] = pk(va, vb);
        }
        // layer 3 logits
        float lgl[3], lgh[3];
#pragma unroll
        for (int o = 0; o < 3; o++) {
            const float* r = &P[184 + 12 * o];
            float4 wA = *(const float4*)r;
            float4 wB = *(const float4*)(r + 4);
            float2 wC = *(const float2*)(r + 8);
            float bb = P[220 + o];
            float pa = fmaf(wA.x, h2a[0], fmaf(wA.z, h2a[2],
                       fmaf(wB.x, h2a[4], fmaf(wB.z, h2a[6], wC.x * h2a[8]))));
            float qa = fmaf(wA.y, h2a[1], fmaf(wA.w, h2a[3],
                       fmaf(wB.y, h2a[5], fmaf(wB.w, h2a[7],
                       fmaf(wC.y, h2a[9], bb)))));
            lgl[o] = pa + qa;
            float pb = fmaf(wA.x, h2b[0], fmaf(wA.z, h2b[2],
                       fmaf(wB.x, h2b[4], fmaf(wB.z, h2b[6], wC.x * h2b[8]))));
            float qb = fmaf(wA.y, h2b[1], fmaf(wA.w, h2b[3],
                       fmaf(wB.y, h2b[5], fmaf(wB.w, h2b[7],
                       fmaf(wC.y, h2b[9], bb)))));
            lgh[o] = pb + qb;
        }
        // softmax + CE (both samples always valid here)
        float d00, d01, d02, d10, d11, d12;
        {
            float mm = fmaxf(lgl[0], fmaxf(lgl[1], lgl[2]));
            float e0 = __expf(lgl[0] - mm), e1 = __expf(lgl[1] - mm), e2 = __expf(lgl[2] - mm);
            float sm = e0 + e1 + e2, iv = __fdividef(1.f, sm);
            int y = y01.x;
            float ly = (y == 0) ? lgl[0] : ((y == 1) ? lgl[1] : lgl[2]);
            l0acc += (mm - ly) + __logf(sm);
            d00 = (e0 * iv - (y == 0 ? 1.f : 0.f)) * invN;
            d01 = (e1 * iv - (y == 1 ? 1.f : 0.f)) * invN;
            d02 = (e2 * iv - (y == 2 ? 1.f : 0.f)) * invN;
        }
        {
            float mm = fmaxf(lgh[0], fmaxf(lgh[1], lgh[2]));
            float e0 = __expf(lgh[0] - mm), e1 = __expf(lgh[1] - mm), e2 = __expf(lgh[2] - mm);
            float sm = e0 + e1 + e2, iv = __fdividef(1.f, sm);
            int y = y01.y;
            float ly = (y == 0) ? lgh[0] : ((y == 1) ? lgh[1] : lgh[2]);
            l1acc += (mm - ly) + __logf(sm);
            d10 = (e0 * iv - (y == 0 ? 1.f : 0.f)) * invN;
            d11 = (e1 * iv - (y == 1 ? 1.f : 0.f)) * invN;
            d12 = (e2 * iv - (y == 2 ? 1.f : 0.f)) * invN;
        }
        *(u64*)&recW[45 * RSC + cj] = pk(d00, d10);
        *(u64*)&recW[50 * RSC + cj] = pk(d01, d11);
        *(u64*)&recW[47 * RSC + cj] = pk(d02, d12);

        // backward
        float dha[10], dhb[10];
#pragma unroll
        for (int h = 0; h < 10; h++) { dha[h] = 0.f; dhb[h] = 0.f; }
#pragma unroll
        for (int g = 0; g < 10; g++) {
            float4 wt = *(const float4*)&P[224 + 4 * g];
            float dga = fmaf(wt.x, d00, fmaf(wt.y, d01, wt.z * d02));
            float dgb = fmaf(wt.x, d10, fmaf(wt.y, d11, wt.z * d12));
            dga = (h2a[g] > 0.f) ? dga : 0.f;
            dgb = (h2b[g] > 0.f) ? dgb : 0.f;
            *(u64*)&recW[(20 + g) * RSC + cj] = pk(dga, dgb);
            const float* r = &P[52 + 12 * g];
            float4 wA = *(const float4*)r;
            float4 wB = *(const float4*)(r + 4);
            float2 wC = *(const float2*)(r + 8);
            dha[0] = fmaf(wA.x, dga, dha[0]);
            dha[1] = fmaf(wA.y, dga, dha[1]);
            dha[2] = fmaf(wA.z, dga, dha[2]);
            dha[3] = fmaf(wA.w, dga, dha[3]);
            dha[4] = fmaf(wB.x, dga, dha[4]);
            dha[5] = fmaf(wB.y, dga, dha[5]);
            dha[6] = fmaf(wB.z, dga, dha[6]);
            dha[7] = fmaf(wB.w, dga, dha[7]);
            dha[8] = fmaf(wC.x, dga, dha[8]);
            dha[9] = fmaf(wC.y, dga, dha[9]);
            dhb[0] = fmaf(wA.x, dgb, dhb[0]);
            dhb[1] = fmaf(wA.y, dgb, dhb[1]);
            dhb[2] = fmaf(wA.z, dgb, dhb[2]);
            dhb[3] = fmaf(wA.w, dgb, dhb[3]);
            dhb[4] = fmaf(wB.x, dgb, dhb[4]);
            dhb[5] = fmaf(wB.y, dgb, dhb[5]);
            dhb[6] = fmaf(wB.z, dgb, dhb[6]);
            dhb[7] = fmaf(wB.w, dgb, dhb[7]);
            dhb[8] = fmaf(wC.x, dgb, dhb[8]);
            dhb[9] = fmaf(wC.y, dgb, dhb[9]);
        }
#pragma unroll
        for (int h = 0; h < 10; h++) {
            float va = (h1a[h] > 0.f) ? dha[h] : 0.f;
            float vb = (h1b[h] > 0.f) ? dhb[h] : 0.f;
            *(u64*)&recW[h * RSC + cj] = pk(va, vb);
        }
        __syncwarp();

        // ---- minipass: 16 steps ----
#pragma unroll 2
        for (int i = 0; i < 16; i++) {
            ulonglong2 a0 = *(const ulonglong2*)&recW[oa0 + 4 * i];
            ulonglong2 a1 = *(const ulonglong2*)&recW[oa1 + 4 * i];
            ulonglong2 b0 = *(const ulonglong2*)&recW[ob0 + 4 * i];
            ulonglong2 b1 = *(const ulonglong2*)&recW[ob1 + 4 * i];
            m0 = ffma2(a0.x, b0.x, m0); m0 = ffma2(a0.y, b0.y, m0);
            m1 = ffma2(a0.x, b1.x, m1); m1 = ffma2(a0.y, b1.y, m1);
            m2 = ffma2(a1.x, b0.x, m2); m2 = ffma2(a1.y, b0.y, m2);
            m3 = ffma2(a1.x, b1.x, m3); m3 = ffma2(a1.y, b1.y, m3);
            sa0 = add2(sa0, add2(a0.x, a0.y));
            sa1 = add2(sa1, add2(a1.x, a1.y));
            ulonglong2 e0 = *(const ulonglong2*)&recW[oe0 + 4 * i];
            ulonglong2 e1 = *(const ulonglong2*)&recW[oe1 + 4 * i];
            ulonglong2 f0 = *(const ulonglong2*)&recW[of0 + 4 * i];
            ulonglong2 f1 = *(const ulonglong2*)&recW[of1 + 4 * i];
            m4 = ffma2(e0.x, f0.x, m4); m4 = ffma2(e0.y, f0.y, m4);
            m5 = ffma2(e0.x, f1.x, m5); m5 = ffma2(e0.y, f1.y, m5);
            m6 = ffma2(e1.x, f0.x, m6); m6 = ffma2(e1.y, f0.y, m6);
            m7 = ffma2(e1.x, f1.x, m7); m7 = ffma2(e1.y, f1.y, m7);
            se0 = add2(se0, add2(e0.x, e0.y));
            se1 = add2(se1, add2(e1.x, e1.y));
        }
        __syncwarp();   // before next chunk overwrites rec rows
    }

    // ================= chunk 2: scalar body, 22 samples on 22 lanes =========
    {
        const int s = 128 + lane;
        const bool valid = (lane < 22);
        float4 xa = make_float4(0.f, 0.f, 0.f, 0.f);
        int y = 0;
        if (valid) {
            xa = ((const float4*)dx)[s];
            y  = dy[s];
        }
        const float km = valid ? invN : 0.f;
        recW[43 * RSC + lane] = xa.x;
        recW[48 * RSC + lane] = xa.y;
        recW[44 * RSC + lane] = xa.z;
        recW[49 * RSC + lane] = xa.w;

        // layer 1 (scalar)
        float h1a[10];
#pragma unroll
        for (int h = 0; h < 10; h++) {
            float4 w = *(const float4*)&P[4 * h];
            float bb = P[40 + h];
            float pa = fmaf(w.x, xa.x, fmaf(w.y, xa.y, bb));
            float qa = fmaf(w.z, xa.z, w.w * xa.w);
            float va = fmaxf(pa + qa, 0.f);
            h1a[h] = va;
            recW[(10 + h) * RSC + lane] = va;
        }
        // layer 2 (scalar)
        float h2a[10];
#pragma unroll
        for (int g = 0; g < 10; g++) {
            const float* r = &P[52 + 12 * g];
            float4 wA = *(const float4*)r;
            float4 wB = *(const float4*)(r + 4);
            float2 wC = *(const float2*)(r + 8);
            float bb = P[172 + g];
            float pa = fmaf(wA.x, h1a[0], fmaf(wA.z, h1a[2],
                       fmaf(wB.x, h1a[4], fmaf(wB.z, h1a[6], wC.x * h1a[8]))));
            float qa = fmaf(wA.y, h1a[1], fmaf(wA.w, h1a[3],
                       fmaf(wB.y, h1a[5], fmaf(wB.w, h1a[7],
                       fmaf(wC.y, h1a[9], bb)))));
            float va = fmaxf(pa + qa, 0.f);
            h2a[g] = va;
            recW[(30 + g) * RSC + lane] = va;
        }
        // layer 3 logits (scalar)
        float lgl[3];
#pragma unroll
        for (int o = 0; o < 3; o++) {
            const float* r = &P[184 + 12 * o];
            float4 wA = *(const float4*)r;
            float4 wB = *(const float4*)(r + 4);
            float2 wC = *(const float2*)(r + 8);
            float bb = P[220 + o];
            float pa = fmaf(wA.x, h2a[0], fmaf(wA.z, h2a[2],
                       fmaf(wB.x, h2a[4], fmaf(wB.z, h2a[6], wC.x * h2a[8]))));
            float qa = fmaf(wA.y, h2a[1], fmaf(wA.w, h2a[3],
                       fmaf(wB.y, h2a[5], fmaf(wB.w, h2a[7],
                       fmaf(wC.y, h2a[9], bb)))));
            lgl[o] = pa + qa;
        }
        // softmax + CE (masked)
        float d00, d01, d02;
        {
            float mm = fmaxf(lgl[0], fmaxf(lgl[1], lgl[2]));
            float e0 = __expf(lgl[0] - mm), e1 = __expf(lgl[1] - mm), e2 = __expf(lgl[2] - mm);
            float sm = e0 + e1 + e2, iv = __fdividef(1.f, sm);
            float ly = (y == 0) ? lgl[0] : ((y == 1) ? lgl[1] : lgl[2]);
            l0acc += valid ? ((mm - ly) + __logf(sm)) : 0.f;
            d00 = (e0 * iv - (y == 0 ? 1.f : 0.f)) * km;
            d01 = (e1 * iv - (y == 1 ? 1.f : 0.f)) * km;
            d02 = (e2 * iv - (y == 2 ? 1.f : 0.f)) * km;
        }
        recW[45 * RSC + lane] = d00;
        recW[50 * RSC + lane] = d01;
        recW[47 * RSC + lane] = d02;

        // backward (scalar)
        float dha[10];
#pragma unroll
        for (int h = 0; h < 10; h++) dha[h] = 0.f;
#pragma unroll
        for (int g = 0; g < 10; g++) {
            float4 wt = *(const float4*)&P[224 + 4 * g];
            float dga = fmaf(wt.x, d00, fmaf(wt.y, d01, wt.z * d02));
            dga = (h2a[g] > 0.f) ? dga : 0.f;
            recW[(20 + g) * RSC + lane] = dga;
            const float* r = &P[52 + 12 * g];
            float4 wA = *(const float4*)r;
            float4 wB = *(const float4*)(r + 4);
            float2 wC = *(const float2*)(r + 8);
            dha[0] = fmaf(wA.x, dga, dha[0]);
            dha[1] = fmaf(wA.y, dga, dha[1]);
            dha[2] = fmaf(wA.z, dga, dha[2]);
            dha[3] = fmaf(wA.w, dga, dha[3]);
            dha[4] = fmaf(wB.x, dga, dha[4]);
            dha[5] = fmaf(wB.y, dga, dha[5]);
            dha[6] = fmaf(wB.z, dga, dha[6]);
            dha[7] = fmaf(wB.w, dga, dha[7]);
            dha[8] = fmaf(wC.x, dga, dha[8]);
            dha[9] = fmaf(wC.y, dga, dha[9]);
        }
#pragma unroll
        for (int h = 0; h < 10; h++) {
            recW[h * RSC + lane] = (h1a[h] > 0.f) ? dha[h] : 0.f;
        }
        __syncwarp();

        // ---- minipass: 6 steps (cols 0..23; cols 22-23 A-rows are zero) ----
#pragma unroll 2
        for (int i = 0; i < 6; i++) {
            ulonglong2 a0 = *(const ulonglong2*)&recW[oa0 + 4 * i];
            ulonglong2 a1 = *(const ulonglong2*)&recW[oa1 + 4 * i];
            ulonglong2 b0 = *(const ulonglong2*)&recW[ob0 + 4 * i];
            ulonglong2 b1 = *(const ulonglong2*)&recW[ob1 + 4 * i];
            m0 = ffma2(a0.x, b0.x, m0); m0 = ffma2(a0.y, b0.y, m0);
            m1 = ffma2(a0.x, b1.x, m1); m1 = ffma2(a0.y, b1.y, m1);
            m2 = ffma2(a1.x, b0.x, m2); m2 = ffma2(a1.y, b0.y, m2);
            m3 = ffma2(a1.x, b1.x, m3); m3 = ffma2(a1.y, b1.y, m3);
            sa0 = add2(sa0, add2(a0.x, a0.y));
            sa1 = add2(sa1, add2(a1.x, a1.y));
            ulonglong2 e0 = *(const ulonglong2*)&recW[oe0 + 4 * i];
            ulonglong2 e1 = *(const ulonglong2*)&recW[oe1 + 4 * i];
            ulonglong2 f0 = *(const ulonglong2*)&recW[of0 + 4 * i];
            ulonglong2 f1 = *(const ulonglong2*)&recW[of1 + 4 * i];
            m4 = ffma2(e0.x, f0.x, m4); m4 = ffma2(e0.y, f0.y, m4);
            m5 = ffma2(e0.x, f1.x, m5); m5 = ffma2(e0.y, f1.y, m5);
            m6 = ffma2(e1.x, f0.x, m6); m6 = ffma2(e1.y, f0.y, m6);
            m7 = ffma2(e1.x, f1.x, m7); m7 = ffma2(e1.y, f1.y, m7);
            se0 = add2(se0, add2(e0.x, e0.y));
            se1 = add2(se1, add2(e1.x, e1.y));
        }
    }

    // ---- finalize grads, sumsq ----
    float ssq = 0.f;
    float* gout = wout + 193;
    float lo, hi, v;
#define EMIT(ACC, IDX) do { upk(ACC, lo, hi); v = lo + hi; \
        gout[(IDX)] = v; ssq = fmaf(v, v, ssq); } while (0)
    if (lane < 25) {
        int q = lane / 5, r = lane % 5;
        EMIT(m0, 50 + 10 * q + r);
        EMIT(m1, 55 + 10 * q + r);
        EMIT(m2, 100 + 10 * q + r);
        EMIT(m3, 105 + 10 * q + r);
        if (r == 0) { EMIT(sa0, 150 + q); EMIT(sa1, 155 + q); }
    }
    if (lane < 10) {
        int a = lane >> 1, bq = lane & 1;
        int bs = 4 * a + 2 * bq;
        EMIT(m4, bs); EMIT(m5, bs + 1); EMIT(m6, bs + 20); EMIT(m7, bs + 21);
        if (bq == 0) { EMIT(se0, 40 + a); EMIT(se1, 45 + a); }
    } else if (lane < 20) {
        int l = lane - 10, p = l / 5, qh = l % 5;
        if (p == 0) {
            EMIT(m4, 160 + qh); EMIT(m5, 165 + qh);
            EMIT(m6, 170 + qh); EMIT(m7, 175 + qh);
            if (qh == 0) { EMIT(se0, 190); EMIT(se1, 191); }
        } else {
            EMIT(m4, 180 + qh); EMIT(m5, 185 + qh);
            if (qh == 0) { EMIT(se0, 192); }
        }
    }
#undef EMIT

    float lossacc = l0acc + l1acc;
    lossacc += __shfl_xor_sync(0xffffffffu, lossacc, 16);
    lossacc += __shfl_xor_sync(0xffffffffu, lossacc, 8);
    lossacc += __shfl_xor_sync(0xffffffffu, lossacc, 4);
    lossacc += __shfl_xor_sync(0xffffffffu, lossacc, 2);
    lossacc += __shfl_xor_sync(0xffffffffu, lossacc, 1);
    const float loss_b = lossacc * invN;

    ssq += __shfl_xor_sync(0xffffffffu, ssq, 16);
    ssq += __shfl_xor_sync(0xffffffffu, ssq, 8);
    ssq += __shfl_xor_sync(0xffffffffu, ssq, 4);
    ssq += __shfl_xor_sync(0xffffffffu, ssq, 2);
    ssq += __shfl_xor_sync(0xffffffffu, ssq, 1);

    if (lane == 0) {
        atomicAdd(&g_sumsq, ssq);
        wout[386] = loss_b;
        wout[387] = clip1e4(fv[b] - loss_b);
    }
}

// Apply global grad-norm clip coefficient to the grad columns [193, 386).
__global__ void k_scale(float* __restrict__ out) {
    const float coef = fminf(1.f, 10.f / (sqrtf(g_sumsq) + 1e-6f));
    const int b = blockIdx.x;
    const int k = threadIdx.x;
    if (k < 193) {
        size_t idx = (size_t)b * 388 + 193 + k;
        out[idx] *= coef;
    }
}

extern "C" void kernel_launch(void* const* d_in, const int* in_sizes, int n_in,
                              void* d_out, int out_size)
{
    const float* W1 = (const float*)d_in[0];
    const float* b1 = (const float*)d_in[1];
    const float* W2 = (const float*)d_in[2];
    const float* b2 = (const float*)d_in[3];
    const float* W3 = (const float*)d_in[4];
    const float* b3 = (const float*)d_in[5];
    const float* G1 = (const float*)d_in[6];
    const float* G2 = (const float*)d_in[7];
    const float* G3 = (const float*)d_in[8];
    const float* G4 = (const float*)d_in[9];
    const float* G5 = (const float*)d_in[10];
    const float* G6 = (const float*)d_in[11];
    const float* dx = (const float*)d_in[12];
    const float* fv = (const float*)d_in[13];
    const int*   dy = (const int*)d_in[14];
    const int*   ss = (const int*)d_in[15];
    float* out = (float*)d_out;

    const int B = in_sizes[13];   // func_val is [B]

    static int carveout_set = 0;
    if (!carveout_set) {
        cudaFuncSetAttribute(k_main,
                             cudaFuncAttributePreferredSharedMemoryCarveout,
                             cudaSharedmemCarveoutMaxShared);
        carveout_set = 1;
    }

    // g_sumsq is 0 on entry: static init on first call, k_zero (below) after.
    k_main<<<B / WPB, BDIM>>>(W1, b1, W2, b2, W3, b3,
                              G1, G2, G3, G4, G5, G6,
                              dx, fv, dy, ss, out);
    k_scale<<<B, 224>>>(out);
    k_zero<<<1, 1>>>();          // reset for the next (graph-replayed) call
}